// round 17
// baseline (speedup 1.0000x reference)
#include <cuda_runtime.h>
#include <math.h>

#define HD 512
#define WD 512
#define BD 32
#define NRING 257      // rings 0..256
#define NBINS 258      // +1 drop bin (r > 256)
#define P2_BLOCKS_X 65 // ceil(257/4)
#define P2_NBLOCKS (P2_BLOCKS_X * BD)

#define PIDX(i) ((i) + ((i) >> 3))   // padded smem index, stride-9 per 8

// Transposed row-FFT intermediate: g_fftT[b][w][h] (complex). 64 MB.
__device__ __align__(16) float2 g_fftT[(size_t)BD * WD * HD];
// Ring accumulators [r*BD+b] = {Cr,Ci,C1,C2}. Zero at load; last pass2 block re-zeros.
__device__ float4 g_bins[NBINS * BD];
// completion counter for fused finalization (reset each run by last block)
__device__ unsigned g_done;

__device__ __forceinline__ float2 cadd(float2 a, float2 b){ return make_float2(a.x+b.x, a.y+b.y); }
__device__ __forceinline__ float2 csub(float2 a, float2 b){ return make_float2(a.x-b.x, a.y-b.y); }
__device__ __forceinline__ float2 cmul(float2 a, float2 b){ return make_float2(a.x*b.x - a.y*b.y, a.x*b.y + a.y*b.x); }

// twiddle: exp(-2*pi*i*idx/512), idx in [0,512)
__device__ __forceinline__ float2 twd(int idx) {
    float s, c;
    sincospif(-(float)idx / 256.0f, &s, &c);
    return make_float2(c, s);
}

// 8-point DFT, forward.
__device__ __forceinline__ void dft8(const float2 a[8], float2 b[8]) {
    float2 t0 = cadd(a[0], a[4]), t1 = csub(a[0], a[4]);
    float2 t2 = cadd(a[2], a[6]), t3 = csub(a[2], a[6]);
    float2 E0 = cadd(t0, t2), E2 = csub(t0, t2);
    float2 E1 = make_float2(t1.x + t3.y, t1.y - t3.x);
    float2 E3 = make_float2(t1.x - t3.y, t1.y + t3.x);
    float2 s0 = cadd(a[1], a[5]), s1 = csub(a[1], a[5]);
    float2 s2 = cadd(a[3], a[7]), s3 = csub(a[3], a[7]);
    float2 O0 = cadd(s0, s2), O2 = csub(s0, s2);
    float2 O1 = make_float2(s1.x + s3.y, s1.y - s3.x);
    float2 O3 = make_float2(s1.x - s3.y, s1.y + s3.x);
    const float r = 0.70710678118654752440f;
    float2 W1 = make_float2(r * (O1.x + O1.y), r * (O1.y - O1.x));
    float2 W2 = make_float2(O2.y, -O2.x);
    float2 W3 = make_float2(r * (O3.y - O3.x), -r * (O3.x + O3.y));
    b[0] = cadd(E0, O0); b[4] = csub(E0, O0);
    b[1] = cadd(E1, W1); b[5] = csub(E1, W1);
    b[2] = cadd(E2, W2); b[6] = csub(E2, W2);
    b[3] = cadd(E3, W3); b[7] = csub(E3, W3);
}

// ---- Pass 1: row FFTs (radix-8, 3 passes), 4 rows/block, transposed store. ----
__global__ void __launch_bounds__(256) pass1_rows(const float* __restrict__ o,
                                                  const float* __restrict__ t) {
    __shared__ float2 buf[4][576];
    __shared__ float2 sTwB[64];
    __shared__ float2 sTwC[448];
    int tid = threadIdx.x;
    int f = tid >> 6, j = tid & 63;

    for (int m = tid; m < 56; m += 256) {
        int i = (m >> 3) + 1, k = m & 7;
        sTwB[m] = twd(8 * i * k);
    }
    for (int m = tid; m < 448; m += 256) {
        int i = (m >> 6) + 1, jj = m & 63;
        sTwC[m] = twd(i * jj);
    }

    int bx = blockIdx.x;
    int b  = bx >> 7;
    int r0 = (bx & 127) << 2;
    int gr = (b << 9) + r0 + f;
    const float* op = o + (size_t)gr * WD;
    const float* tp = t + (size_t)gr * WD;

    float2 v[8], w[8];
    #pragma unroll
    for (int i = 0; i < 8; i++)
        v[i] = make_float2(op[j + 64 * i], tp[j + 64 * i]);   // z = o + i*t

    dft8(v, w);                                               // pass A
    __syncthreads();                                          // tw tables ready
    #pragma unroll
    for (int u = 0; u < 8; u++) buf[f][PIDX(8 * j + u)] = w[u];
    __syncthreads();
    int k = j & 7;                                            // pass B
    #pragma unroll
    for (int i = 0; i < 8; i++) v[i] = buf[f][PIDX(j + 64 * i)];
    #pragma unroll
    for (int i = 1; i < 8; i++) v[i] = cmul(v[i], sTwB[(i - 1) * 8 + k]);
    dft8(v, w);
    __syncthreads();
    {
        int base = (j & ~7) * 8 + k;
        #pragma unroll
        for (int u = 0; u < 8; u++) buf[f][PIDX(base + 8 * u)] = w[u];
    }
    __syncthreads();
    #pragma unroll
    for (int i = 0; i < 8; i++) v[i] = buf[f][PIDX(j + 64 * i)];   // pass C
    #pragma unroll
    for (int i = 1; i < 8; i++) v[i] = cmul(v[i], sTwC[(i - 1) * 64 + j]);
    dft8(v, w);
    __syncthreads();
    #pragma unroll
    for (int u = 0; u < 8; u++) buf[f][PIDX(j + 64 * u)] = w[u];
    __syncthreads();

    float4* outp = (float4*)(g_fftT + (size_t)b * WD * HD);
    #pragma unroll
    for (int q = 0; q < 2; q++) {
        int wv = tid + 256 * q;
        float2 q0 = buf[0][PIDX(wv)], q1 = buf[1][PIDX(wv)];
        float2 q2 = buf[2][PIDX(wv)], q3 = buf[3][PIDX(wv)];
        size_t i4 = ((size_t)wv * HD + r0) >> 1;
        outp[i4]     = make_float4(q0.x, q0.y, q1.x, q1.y);
        outp[i4 + 1] = make_float4(q2.x, q2.y, q3.x, q3.y);
    }
}

// ---- Pass 2: 256 threads, 2 pairs concurrent x 2 iters, register-run binning. ----
__global__ void __launch_bounds__(256) pass2_cols(float* __restrict__ out) {
    __shared__ __align__(16) float2 buf[4][576];
    __shared__ float2 sTwB[64];
    __shared__ float2 sTwC[448];
    __shared__ float  sbin[NBINS * 4];
    __shared__ unsigned sIsLast;

    int tid = threadIdx.x;
    int quarter = tid >> 6;          // 0..3: FFT unit
    int pairq   = tid >> 7;          // 0: pair A, 1: pair B
    int half    = quarter & 1;       // column within pair (warp-uniform)
    int j = tid & 63;
    int b = blockIdx.y;
    unsigned lane = tid & 31;
    const unsigned full = 0xffffffffu;

    for (int m = tid; m < 56; m += 256) {
        int i = (m >> 3) + 1, k = m & 7;
        sTwB[m] = twd(8 * i * k);
    }
    for (int m = tid; m < 448; m += 256) {
        int i = (m >> 6) + 1, jj = m & 63;
        sTwC[m] = twd(i * jj);
    }
    for (int m = tid; m < NBINS * 4; m += 256) sbin[m] = 0.0f;

    #pragma unroll 1
    for (int it = 0; it < 2; it++) {
        int p = blockIdx.x * 4 + it * 2 + pairq;     // this quarter's pair
        bool valid = (p < NRING);
        int w2 = (512 - p) & 511;
        bool self = (w2 == p);
        int col = half ? w2 : p;                     // always in [0,511] (p<=259)
        const float2* cp = g_fftT + ((size_t)b * WD + col) * HD;

        float2 v[8], w[8];
        __syncthreads();                  // tw tables ready / buf free from prev iter
        #pragma unroll
        for (int i = 0; i < 8; i++) v[i] = cp[j + 64 * i];

        dft8(v, w);                       // pass A
        #pragma unroll
        for (int u = 0; u < 8; u++) buf[quarter][PIDX(8 * j + u)] = w[u];
        __syncthreads();
        int k = j & 7;                    // pass B
        #pragma unroll
        for (int i = 0; i < 8; i++) v[i] = buf[quarter][PIDX(j + 64 * i)];
        #pragma unroll
        for (int i = 1; i < 8; i++) v[i] = cmul(v[i], sTwB[(i - 1) * 8 + k]);
        dft8(v, w);
        __syncthreads();
        {
            int base = (j & ~7) * 8 + k;
            #pragma unroll
            for (int u = 0; u < 8; u++) buf[quarter][PIDX(base + 8 * u)] = w[u];
        }
        __syncthreads();
        #pragma unroll
        for (int i = 0; i < 8; i++) v[i] = buf[quarter][PIDX(j + 64 * i)];  // pass C
        #pragma unroll
        for (int i = 1; i < 8; i++) v[i] = cmul(v[i], sTwC[(i - 1) * 64 + j]);
        dft8(v, w);
        __syncthreads();
        // final store: primary column unpadded; mirror column stored REVERSED
        // (FBrev[kh] = FB[(512-kh)&511]) so binning reads are contiguous.
        #pragma unroll
        for (int u = 0; u < 8; u++) {
            int dst = j + 64 * u;
            if (half) dst = (512 - dst) & 511;   // warp-uniform select
            buf[quarter][dst] = w[u];
        }
        __syncthreads();

        // ---- binning: threads 0-127 bin pair A, 128-255 pair B.
        //      thread lt handles contiguous kh = 4*lt .. 4*lt+3; runs of equal
        //      ring accumulate in registers, flushed on change (few atomics). ----
        if (valid) {
            int lt = tid & 127;
            const float4* FA4 = (const float4*)(buf[pairq * 2]);
            const float4* FB4 = (const float4*)(buf[pairq * 2 + 1]);
            float4 A01 = FA4[lt * 2], A23 = FA4[lt * 2 + 1];
            float4 B01 = FB4[lt * 2], B23 = FB4[lt * 2 + 1];
            float2 fa[4] = { make_float2(A01.x, A01.y), make_float2(A01.z, A01.w),
                             make_float2(A23.x, A23.y), make_float2(A23.z, A23.w) };
            float2 fb[4] = { make_float2(B01.x, B01.y), make_float2(B01.z, B01.w),
                             make_float2(B23.x, B23.y), make_float2(B23.z, B23.w) };

            int fw = (p <= 255) ? p : p - 512;
            float fw2 = (float)(fw * fw);
            const float scale = 1.0f / (512.0f * 512.0f);
            float mulf = self ? 1.0f : 2.0f;
            int kh0 = lt * 4;

            int rcur = -1;
            float a0 = 0.f, a1 = 0.f, a2 = 0.f, a3 = 0.f;
            #pragma unroll
            for (int i = 0; i < 4; i++) {
                int kh = kh0 + i;
                float2 P  = fa[i];                   // Fz(kh, p)
                float2 Mc = fb[i];                   // Fz(-kh, -p) via reversed store
                float px = P.x * scale,  py = P.y * scale;
                float mx = Mc.x * scale, my = -Mc.y * scale;   // conj
                float f1x = 0.5f * (px + mx), f1y = 0.5f * (py + my);
                float dx  = 0.5f * (px - mx), dy  = 0.5f * (py - my);
                float f2x = dy, f2y = -dx;
                float av  = mulf * (f1x * f2x + f1y * f2y);
                float c1  = mulf * (f1x * f1x + f1y * f1y);
                float c2  = mulf * (f2x * f2x + f2y * f2y);
                float bv  = f1y * f2x - f1x * f2y;

                int fh = (kh <= 255) ? kh : kh - 512;
                float rr = sqrtf((float)(fh * fh) + fw2);
                int r = (int)rintf(rr);              // round-half-even == jnp.round
                if (r > 256) r = 257;

                if (r != rcur) {
                    if (rcur >= 0) {
                        atomicAdd(&sbin[rcur * 4 + 0], a0);
                        atomicAdd(&sbin[rcur * 4 + 2], a1);
                        atomicAdd(&sbin[rcur * 4 + 3], a2);
                        if (self) atomicAdd(&sbin[rcur * 4 + 1], a3);
                    }
                    rcur = r; a0 = av; a1 = c1; a2 = c2; a3 = bv;
                } else {
                    a0 += av; a1 += c1; a2 += c2; a3 += bv;
                }
            }
            atomicAdd(&sbin[rcur * 4 + 0], a0);
            atomicAdd(&sbin[rcur * 4 + 2], a1);
            atomicAdd(&sbin[rcur * 4 + 3], a2);
            if (self) atomicAdd(&sbin[rcur * 4 + 1], a3);
        }
    }
    __syncthreads();

    // ---- flush accumulated bins (4 pairs) to global ----
    float* gb = (float*)g_bins;
    for (int i = tid; i < NBINS * 4; i += 256) {
        float v2 = sbin[i];
        if (v2 != 0.0f) {
            int r = i >> 2, c = i & 3;
            atomicAdd(&gb[(r * BD + b) * 4 + c], v2);
        }
    }
    __syncthreads();

    // ---- last block finalizes: frc + mean, re-zero bins & counter ----
    if (tid == 0) {
        __threadfence();
        unsigned v = atomicAdd(&g_done, 1u);
        sIsLast = (v == (unsigned)(P2_NBLOCKS - 1));
    }
    __syncthreads();
    if (sIsLast) {
        float acc = 0.0f;
        const float4 zero4 = make_float4(0.f, 0.f, 0.f, 0.f);
        for (int i = tid; i < NBINS * BD; i += 256) {
            float4 s = __ldcg(&g_bins[i]);
            __stcg(&g_bins[i], zero4);
            int r = i / BD;
            if (r < NRING) {
                float frc = sqrtf(s.x * s.x + s.y * s.y) / (sqrtf(s.z * s.w) + 1e-8f);
                float d = 1.0f - frc;
                acc += d * d;
            }
        }
        #pragma unroll
        for (int o = 16; o > 0; o >>= 1)
            acc += __shfl_xor_sync(full, acc, o);
        __shared__ float red[8];
        if (lane == 0) red[tid >> 5] = acc;
        __syncthreads();
        if (tid < 32) {
            float v = (tid < 8) ? red[tid] : 0.0f;
            #pragma unroll
            for (int o = 4; o > 0; o >>= 1)
                v += __shfl_xor_sync(full, v, o);
            if (tid == 0) {
                out[0] = v / (float)(NRING * BD);
                atomicExch(&g_done, 0u);
            }
        }
    }
}

extern "C" void kernel_launch(void* const* d_in, const int* in_sizes, int n_in,
                              void* d_out, int out_size) {
    const float* o = (const float*)d_in[0];   // output (32,1,512,512) f32
    const float* t = (const float*)d_in[1];   // target (32,1,512,512) f32
    float* out = (float*)d_out;

    // carveout hint: prefer max shared so smem (not carveout) sets blocks/SM
    cudaFuncSetAttribute(pass1_rows, cudaFuncAttributePreferredSharedMemoryCarveout,
                         cudaSharedmemCarveoutMaxShared);
    cudaFuncSetAttribute(pass2_cols, cudaFuncAttributePreferredSharedMemoryCarveout,
                         cudaSharedmemCarveoutMaxShared);

    pass1_rows<<<BD * HD / 4, 256>>>(o, t);
    dim3 g2(P2_BLOCKS_X, BD);
    pass2_cols<<<g2, 256>>>(out);
}